// round 5
// baseline (speedup 1.0000x reference)
#include <cuda_runtime.h>
#include <float.h>

// Fused sRGB->CIELab + per-image L min-max normalization, SINGLE kernel.
// One CTA per image (1024 threads, 192KB smem):
//  phase 1: read image once (float4 streaming loads), linearize sRGB (6 MUFU/px),
//           stash rl/gl/bl in 3 float4-planar smem arrays, track Y min/max
//           (L is strictly monotonic in Y).
//  reduce : warp shuffle + smem across 32 warps.
//  phase 2: reload lin from smem (LDS.128), 3x3 matrix + cbrt (6 MUFU/px),
//           write coalesced float4 streaming stores.
// DRAM traffic = exactly 1 read + 1 write (201 MB total).

#define NPIX    16384              // 128*128
#define NIMG    512
#define THREADS 1024
#define NGRP    (NPIX / 4)                 // 4096 pixel-groups of 4
#define GROUPS  (NPIX / (THREADS * 4))     // 4 groups per thread

__device__ __forceinline__ float mufu_lg2(float x) {
    float r; asm("lg2.approx.f32 %0, %1;" : "=f"(r) : "f"(x)); return r;
}
__device__ __forceinline__ float mufu_ex2(float x) {
    float r; asm("ex2.approx.f32 %0, %1;" : "=f"(r) : "f"(x)); return r;
}
__device__ __forceinline__ float mufu_rcp(float x) {
    float r; asm("rcp.approx.f32 %0, %1;" : "=f"(r) : "f"(x)); return r;
}

__device__ __forceinline__ float srgb_lin(float c) {
    // ((c + 0.055)/1.055)^2.4 if c > 0.04045 else c/12.92
    float t = fmaf(c, 1.0f / 1.055f, 0.055f / 1.055f);
    float p = mufu_ex2(2.4f * mufu_lg2(t));
    return (c > 0.04045f) ? p : c * (1.0f / 12.92f);
}

__device__ __forceinline__ float xyz_f(float t) {
    // cbrt(t) if t > 0.008856 else 7.787t + 16/116 (monotonic, continuous)
    float cr = mufu_ex2((1.0f / 3.0f) * mufu_lg2(t));
    return (t > 0.008856f) ? cr : fmaf(t, 7.787f, 16.0f / 116.0f);
}

__global__ void __launch_bounds__(THREADS, 1)
rgb2lab_fused_kernel(const float* __restrict__ x, float* __restrict__ out) {
    extern __shared__ float4 smem4[];
    float4* sR = smem4;                  // [4096] rl plane (float4 of 4 px)
    float4* sG = smem4 + NGRP;           // [4096]
    float4* sB = smem4 + 2 * NGRP;       // [4096]
    float*  red = (float*)(smem4 + 3 * NGRP);  // [66] reduction scratch

    const int img = blockIdx.x;
    const int tid = threadIdx.x;

    const int base4 = img * (NPIX * 3 / 4);       // float4 units, fits int
    const float4* in4 = (const float4*)x   + base4;
    float4*       o4  = (float4*)      out + base4;

    float ymin = FLT_MAX, ymax = -FLT_MAX;

    // ---------------- phase 1: linearize, stash, Y min/max ----------------
    #pragma unroll
    for (int j = 0; j < GROUPS; j++) {
        int gi = tid + j * THREADS;               // pixel-group index
        float4 v0 = __ldcs(&in4[gi * 3 + 0]);
        float4 v1 = __ldcs(&in4[gi * 3 + 1]);
        float4 v2 = __ldcs(&in4[gi * 3 + 2]);

        // pixels: (v0.x v0.y v0.z) (v0.w v1.x v1.y) (v1.z v1.w v2.x) (v2.y v2.z v2.w)
        float4 r4 = make_float4(srgb_lin(v0.x), srgb_lin(v0.w), srgb_lin(v1.z), srgb_lin(v2.y));
        float4 g4 = make_float4(srgb_lin(v0.y), srgb_lin(v1.x), srgb_lin(v1.w), srgb_lin(v2.z));
        float4 b4 = make_float4(srgb_lin(v0.z), srgb_lin(v1.y), srgb_lin(v2.x), srgb_lin(v2.w));

        sR[gi] = r4;  sG[gi] = g4;  sB[gi] = b4;

        float y0 = fmaf(0.212671f, r4.x, fmaf(0.715160f, g4.x, 0.072169f * b4.x));
        float y1 = fmaf(0.212671f, r4.y, fmaf(0.715160f, g4.y, 0.072169f * b4.y));
        float y2 = fmaf(0.212671f, r4.z, fmaf(0.715160f, g4.z, 0.072169f * b4.z));
        float y3 = fmaf(0.212671f, r4.w, fmaf(0.715160f, g4.w, 0.072169f * b4.w));
        ymin = fminf(fminf(fminf(ymin, y0), fminf(y1, y2)), y3);
        ymax = fmaxf(fmaxf(fmaxf(ymax, y0), fmaxf(y1, y2)), y3);
    }

    // ---------------- min/max reduction (32 warps) ----------------
    #pragma unroll
    for (int off = 16; off > 0; off >>= 1) {
        ymin = fminf(ymin, __shfl_xor_sync(0xffffffffu, ymin, off));
        ymax = fmaxf(ymax, __shfl_xor_sync(0xffffffffu, ymax, off));
    }
    int lane = tid & 31, wid = tid >> 5;
    if (lane == 0) { red[wid] = ymin; red[32 + wid] = ymax; }
    __syncthreads();
    if (tid == 0) {
        float mn = red[0], mx = red[32];
        #pragma unroll
        for (int i = 1; i < 32; i++) {
            mn = fminf(mn, red[i]);
            mx = fmaxf(mx, red[32 + i]);
        }
        float fmn = xyz_f(mn);
        red[64] = fmn;
        red[65] = mufu_rcp(xyz_f(mx) - fmn);
    }
    __syncthreads();
    const float fmin = red[64];
    const float sf   = red[65];

    // ---------------- phase 2: matrix + cbrt + normalized write ----------------
    #pragma unroll
    for (int j = 0; j < GROUPS; j++) {
        int gi = tid + j * THREADS;
        float4 r4 = sR[gi];
        float4 g4 = sG[gi];
        float4 b4 = sB[gi];

        const float M00 = 0.412453f / 0.95047f, M01 = 0.357580f / 0.95047f, M02 = 0.180423f / 0.95047f;
        const float M10 = 0.212671f,            M11 = 0.715160f,            M12 = 0.072169f;
        const float M20 = 0.019334f / 1.08883f, M21 = 0.119193f / 1.08883f, M22 = 0.950227f / 1.08883f;

        float L[4], A[4], B[4];
        const float* rr = &r4.x; const float* gg = &g4.x; const float* bb = &b4.x;
        #pragma unroll
        for (int p = 0; p < 4; p++) {
            float rl = rr[p], gl = gg[p], bl = bb[p];
            float X = fmaf(M00, rl, fmaf(M01, gl, M02 * bl));
            float Y = fmaf(M10, rl, fmaf(M11, gl, M12 * bl));
            float Z = fmaf(M20, rl, fmaf(M21, gl, M22 * bl));
            float fx = xyz_f(X);
            float fy = xyz_f(Y);
            float fz = xyz_f(Z);
            L[p] = (fy - fmin) * sf;
            A[p] = fmaf(fx - fy, 500.0f / 255.0f, 128.0f / 255.0f);
            B[p] = fmaf(fy - fz, 200.0f / 255.0f, 128.0f / 255.0f);
        }

        __stcs(&o4[gi * 3 + 0], make_float4(L[0], A[0], B[0], L[1]));
        __stcs(&o4[gi * 3 + 1], make_float4(A[1], B[1], L[2], A[2]));
        __stcs(&o4[gi * 3 + 2], make_float4(B[2], L[3], A[3], B[3]));
    }
}

extern "C" void kernel_launch(void* const* d_in, const int* in_sizes, int n_in,
                              void* d_out, int out_size) {
    const float* x   = (const float*)d_in[0];
    float*       out = (float*)d_out;

    const int smem_bytes = 3 * NGRP * sizeof(float4) + 66 * sizeof(float); // 196,872 B
    cudaFuncSetAttribute(rgb2lab_fused_kernel,
                         cudaFuncAttributeMaxDynamicSharedMemorySize, smem_bytes);

    rgb2lab_fused_kernel<<<NIMG, THREADS, smem_bytes>>>(x, out);
}

// round 6
// speedup vs baseline: 1.0829x; 1.0829x over previous
#include <cuda_runtime.h>
#include <float.h>

// Fused sRGB->CIELab + per-image L min-max normalization, single kernel with
// cross-CTA per-image sync. 8 CTAs per image; each CTA:
//   phase1: read own 2048 px ONCE (__ldcs), linearize (6 MUFU/px), stash lin
//           in smem (24KB), publish Y min/max partial (release counter).
//   spin  : one warp acquire-spins until all 8 partials for the image landed.
//   phase2: matrix + cbrt from own smem, coalesced float4 writes.
// DRAM traffic = 1 read + 1 write (201 MB). 8 CTAs/SM overlap phases.

#define NPIX    16384
#define NIMG    512
#define SUBS    8                      // CTAs per image
#define THREADS 256
#define PX_CTA  (NPIX / SUBS)          // 2048 px per CTA
#define NG_CTA  (PX_CTA / 4)           // 512 pixel-groups per CTA
#define GROUPS  (NG_CTA / THREADS)     // 2 groups per thread

__device__ float g_pmin[NIMG * SUBS];
__device__ float g_pmax[NIMG * SUBS];
__device__ int   g_cnt[NIMG];          // reset to 0 by memset node each replay

__device__ __forceinline__ float mufu_lg2(float x) {
    float r; asm("lg2.approx.f32 %0, %1;" : "=f"(r) : "f"(x)); return r;
}
__device__ __forceinline__ float mufu_ex2(float x) {
    float r; asm("ex2.approx.f32 %0, %1;" : "=f"(r) : "f"(x)); return r;
}
__device__ __forceinline__ float mufu_rcp(float x) {
    float r; asm("rcp.approx.f32 %0, %1;" : "=f"(r) : "f"(x)); return r;
}

__device__ __forceinline__ float srgb_lin(float c) {
    float t = fmaf(c, 1.0f / 1.055f, 0.055f / 1.055f);
    float p = mufu_ex2(2.4f * mufu_lg2(t));
    return (c > 0.04045f) ? p : c * (1.0f / 12.92f);
}

__device__ __forceinline__ float xyz_f(float t) {
    float cr = mufu_ex2((1.0f / 3.0f) * mufu_lg2(t));
    return (t > 0.008856f) ? cr : fmaf(t, 7.787f, 16.0f / 116.0f);
}

__global__ void __launch_bounds__(THREADS, 8)
rgb2lab_sync_kernel(const float* __restrict__ x, float* __restrict__ out) {
    __shared__ float4 sR[NG_CTA];      // 8KB  linearized R plane
    __shared__ float4 sG[NG_CTA];      // 8KB
    __shared__ float4 sB[NG_CTA];      // 8KB
    __shared__ float  red[18];         // 8 warp-mins, 8 warp-maxs, fmin, sf

    const int bid = blockIdx.x;
    const int img = bid >> 3;
    const int sub = bid & 7;
    const int tid = threadIdx.x;

    const int base4 = img * (NPIX * 3 / 4) + sub * (PX_CTA * 3 / 4);
    const float4* in4 = (const float4*)x   + base4;
    float4*       o4  = (float4*)      out + base4;

    float ymin = FLT_MAX, ymax = -FLT_MAX;

    // ---------------- phase 1: read once, linearize, stash, Y min/max ----
    #pragma unroll
    for (int j = 0; j < GROUPS; j++) {
        int gi = tid + j * THREADS;                // 0 .. 511
        float4 v0 = __ldcs(&in4[gi * 3 + 0]);
        float4 v1 = __ldcs(&in4[gi * 3 + 1]);
        float4 v2 = __ldcs(&in4[gi * 3 + 2]);

        float4 r4 = make_float4(srgb_lin(v0.x), srgb_lin(v0.w), srgb_lin(v1.z), srgb_lin(v2.y));
        float4 g4 = make_float4(srgb_lin(v0.y), srgb_lin(v1.x), srgb_lin(v1.w), srgb_lin(v2.z));
        float4 b4 = make_float4(srgb_lin(v0.z), srgb_lin(v1.y), srgb_lin(v2.x), srgb_lin(v2.w));

        sR[gi] = r4;  sG[gi] = g4;  sB[gi] = b4;

        float y0 = fmaf(0.212671f, r4.x, fmaf(0.715160f, g4.x, 0.072169f * b4.x));
        float y1 = fmaf(0.212671f, r4.y, fmaf(0.715160f, g4.y, 0.072169f * b4.y));
        float y2 = fmaf(0.212671f, r4.z, fmaf(0.715160f, g4.z, 0.072169f * b4.z));
        float y3 = fmaf(0.212671f, r4.w, fmaf(0.715160f, g4.w, 0.072169f * b4.w));
        ymin = fminf(fminf(fminf(ymin, y0), fminf(y1, y2)), y3);
        ymax = fmaxf(fmaxf(fmaxf(ymax, y0), fmaxf(y1, y2)), y3);
    }

    // ---------------- CTA-local reduce (8 warps) ----------------
    #pragma unroll
    for (int off = 16; off > 0; off >>= 1) {
        ymin = fminf(ymin, __shfl_xor_sync(0xffffffffu, ymin, off));
        ymax = fmaxf(ymax, __shfl_xor_sync(0xffffffffu, ymax, off));
    }
    int lane = tid & 31, wid = tid >> 5;
    if (lane == 0) { red[wid] = ymin; red[8 + wid] = ymax; }
    __syncthreads();

    // ---------------- publish partial + spin for whole image -------------
    if (tid == 0) {
        float mn = red[0], mx = red[8];
        #pragma unroll
        for (int i = 1; i < 8; i++) {
            mn = fminf(mn, red[i]);
            mx = fmaxf(mx, red[8 + i]);
        }
        g_pmin[bid] = mn;
        g_pmax[bid] = mx;
        // release: prior stores visible before counter increment
        asm volatile("red.release.gpu.global.add.s32 [%0], 1;"
                     :: "l"(&g_cnt[img]) : "memory");

        // spin until all 8 partials for this image have landed
        int c;
        do {
            asm volatile("ld.acquire.gpu.global.s32 %0, [%1];"
                         : "=r"(c) : "l"(&g_cnt[img]) : "memory");
            if (c < SUBS) __nanosleep(64);
        } while (c < SUBS);

        float fm = FLT_MAX, fM = -FLT_MAX;
        #pragma unroll
        for (int i = 0; i < SUBS; i++) {
            fm = fminf(fm, g_pmin[img * 8 + i]);
            fM = fmaxf(fM, g_pmax[img * 8 + i]);
        }
        float fmn = xyz_f(fm);
        red[16] = fmn;
        red[17] = mufu_rcp(xyz_f(fM) - fmn);
    }
    __syncthreads();
    const float fmin = red[16];
    const float sf   = red[17];

    // ---------------- phase 2: matrix + cbrt + normalized write ----------
    const float M00 = 0.412453f / 0.95047f, M01 = 0.357580f / 0.95047f, M02 = 0.180423f / 0.95047f;
    const float M10 = 0.212671f,            M11 = 0.715160f,            M12 = 0.072169f;
    const float M20 = 0.019334f / 1.08883f, M21 = 0.119193f / 1.08883f, M22 = 0.950227f / 1.08883f;

    #pragma unroll
    for (int j = 0; j < GROUPS; j++) {
        int gi = tid + j * THREADS;
        float4 r4 = sR[gi];
        float4 g4 = sG[gi];
        float4 b4 = sB[gi];

        float L[4], A[4], B[4];
        const float* rr = &r4.x; const float* gg = &g4.x; const float* bb = &b4.x;
        #pragma unroll
        for (int p = 0; p < 4; p++) {
            float rl = rr[p], gl = gg[p], bl = bb[p];
            float X = fmaf(M00, rl, fmaf(M01, gl, M02 * bl));
            float Y = fmaf(M10, rl, fmaf(M11, gl, M12 * bl));
            float Z = fmaf(M20, rl, fmaf(M21, gl, M22 * bl));
            float fx = xyz_f(X);
            float fy = xyz_f(Y);
            float fz = xyz_f(Z);
            L[p] = (fy - fmin) * sf;
            A[p] = fmaf(fx - fy, 500.0f / 255.0f, 128.0f / 255.0f);
            B[p] = fmaf(fy - fz, 200.0f / 255.0f, 128.0f / 255.0f);
        }

        o4[gi * 3 + 0] = make_float4(L[0], A[0], B[0], L[1]);
        o4[gi * 3 + 1] = make_float4(A[1], B[1], L[2], A[2]);
        o4[gi * 3 + 2] = make_float4(B[2], L[3], A[3], B[3]);
    }
}

extern "C" void kernel_launch(void* const* d_in, const int* in_sizes, int n_in,
                              void* d_out, int out_size) {
    const float* x   = (const float*)d_in[0];
    float*       out = (float*)d_out;

    // reset per-image arrival counters (graph memset node, runs every replay)
    void* cnt_ptr = nullptr;
    cudaGetSymbolAddress(&cnt_ptr, g_cnt);
    cudaMemsetAsync(cnt_ptr, 0, NIMG * sizeof(int));

    rgb2lab_sync_kernel<<<NIMG * SUBS, THREADS>>>(x, out);
}